// round 11
// baseline (speedup 1.0000x reference)
#include <cuda_runtime.h>
#include <cuda_fp16.h>
#include <cstdint>

#define BB 16
#define LL 512
#define DD 256
#define FF 256
#define MM 2048
#define EPSV 1e-5f
#define NCONV 128          // conv blocks in fused grid
#define NREG  2048         // regulate blocks appended to conv1 grid

// ---------------- device scratch ----------------
__device__ __align__(16) __half g_xh[BB * LL * DD];     // x in fp16
__device__ __align__(16) __half g_h1h[BB * LL * FF];    // conv1 output in fp16
// weights in mma-FRAGMENT order: uint4 index = (ks*16 + p)*32 + lane
__device__ __align__(16) uint4 g_B1f[48 * 16 * 32];
__device__ __align__(16) uint4 g_B2f[48 * 16 * 32];
__device__ int g_cs[BB * LL];

// ---------------- helpers ----------------
__device__ __forceinline__ uint32_t smem_u32(const void* p) {
    uint32_t a;
    asm("{ .reg .u64 t; cvta.to.shared.u64 t, %1; cvt.u32.u64 %0, t; }"
        : "=r"(a) : "l"(p));
    return a;
}

__device__ __forceinline__ void cp16(uint32_t dst, const void* src, int valid) {
    int sz = valid ? 16 : 0;
    asm volatile("cp.async.cg.shared.global [%0], [%1], %2, %3;"
                 :: "r"(dst), "l"(src), "n"(16), "r"(sz));
}
__device__ __forceinline__ void cp_commit() {
    asm volatile("cp.async.commit_group;" ::: "memory");
}
__device__ __forceinline__ void cp_wait0() {
    asm volatile("cp.async.wait_group 0;" ::: "memory");
}

__device__ __forceinline__ void ldsm4(uint32_t* r, uint32_t addr) {
    asm volatile("ldmatrix.sync.aligned.m8n8.x4.shared.b16 {%0,%1,%2,%3}, [%4];"
                 : "=r"(r[0]), "=r"(r[1]), "=r"(r[2]), "=r"(r[3]) : "r"(addr));
}

__device__ __forceinline__ void ldg128(uint4& v, const uint4* p) {
    asm volatile("ld.global.nc.v4.u32 {%0,%1,%2,%3}, [%4];"
                 : "=r"(v.x), "=r"(v.y), "=r"(v.z), "=r"(v.w) : "l"(p));
}

__device__ __forceinline__ void mma16816(float* d, const uint32_t* a,
                                         const uint32_t* b) {
    asm volatile(
        "mma.sync.aligned.m16n8k16.row.col.f32.f16.f16.f32 "
        "{%0,%1,%2,%3}, {%4,%5,%6,%7}, {%8,%9}, {%0,%1,%2,%3};"
        : "+f"(d[0]), "+f"(d[1]), "+f"(d[2]), "+f"(d[3])
        : "r"(a[0]), "r"(a[1]), "r"(a[2]), "r"(a[3]), "r"(b[0]), "r"(b[1]));
}

// ---------------- prep: x -> fp16; weights -> fragment-order fp16 ----------
__global__ void prep_convert(const float* __restrict__ x,
                             const float* __restrict__ w1,
                             const float* __restrict__ w2) {
    int i4 = blockIdx.x * 256 + threadIdx.x;   // vec4 index
    if (i4 < BB * LL * DD / 4) {
        float4 v = reinterpret_cast<const float4*>(x)[i4];
        __half h[4];
        h[0] = __float2half(v.x);
        h[1] = __float2half(v.y);
        h[2] = __float2half(v.z);
        h[3] = __float2half(v.w);
        reinterpret_cast<uint2*>(g_xh)[i4] = *(uint2*)h;
    }
    if (i4 < 48 * 16 * 32) {
        int lane = i4 & 31;
        int rest = i4 >> 5;
        int p = rest & 15;
        int ks = rest >> 4;          // 0..47
        int kc = ks / 6, s = ks % 6;
        int tap = s >> 1, ko = s & 1;
        int l4 = lane & 3, lq = lane >> 2;
        int d0 = kc * 32 + ko * 16 + l4 * 2;
        int na = p * 16 + lq, nb = na + 8;
        auto pack = [&](const float* w, int n, int d) -> unsigned {
            __half2 h = __floats2half2_rn(w[n * 768 + d * 3 + tap],
                                          w[n * 768 + (d + 1) * 3 + tap]);
            return *(unsigned*)&h;
        };
        uint4 v1, v2;
        v1.x = pack(w1, na, d0);
        v1.y = pack(w1, na, d0 + 8);
        v1.z = pack(w1, nb, d0);
        v1.w = pack(w1, nb, d0 + 8);
        v2.x = pack(w2, na, d0);
        v2.y = pack(w2, na, d0 + 8);
        v2.z = pack(w2, nb, d0);
        v2.w = pack(w2, nb, d0 + 8);
        g_B1f[i4] = v1;
        g_B2f[i4] = v2;
    }
}

// ---------------- cumsum ----------------
__global__ void cumsum_k(const int* __restrict__ t, int* __restrict__ cs) {
    __shared__ int s[LL];
    int b = blockIdx.x, tid = threadIdx.x;
    s[tid] = t[(b << 9) + tid];
    __syncthreads();
    for (int off = 1; off < LL; off <<= 1) {
        int v = (tid >= off) ? s[tid - off] : 0;
        __syncthreads();
        s[tid] += v;
        __syncthreads();
    }
    cs[(b << 9) + tid] = s[tid];
}

// ---------------- fp16 conv(K=3) (+fused regulate blocks on conv1) --------
// Conv blocks (< NCONV): 64 rows x 256 ch; 16 warps (2m x 8n), warp tile 32x32.
// A smem-resident; B direct-LDG fragment stream, 3-slot register ring.
// Regulate blocks (>= NCONV): 16 warps, each copies one (b,m) row of x.
#define S_PAR   0                  // bias/g/be/lw: 4 x 1KB
#define S_A     4096
#define A_STR   528
#define STATS_B (64 * 264 * 4)     // 67584 (overlaps A region)
#define S_TOTAL (4096 + STATS_B)   // 71680

__global__ void __launch_bounds__(512, 1)
conv_mma(const __half* __restrict__ a_in,
         const uint4* __restrict__ Bf,
         const float* __restrict__ bias,
         const float* __restrict__ gamma,
         const float* __restrict__ beta,
         int mode,
         __half* __restrict__ out_h,
         const float* __restrict__ lw,
         const float* __restrict__ lb,
         float* __restrict__ dup,
         const float* __restrict__ x32,
         const int* __restrict__ cs,
         float* __restrict__ reg_out) {
    extern __shared__ char sm[];
    const int tid = threadIdx.x;
    const int lane = tid & 31;
    const int wid = tid >> 5;

    // ---------------- regulate blocks ----------------
    if (blockIdx.x >= NCONV) {
        int gm = (blockIdx.x - NCONV) * 16 + wid;   // 0 .. B*M-1
        int b = gm >> 11;
        int m = gm & (MM - 1);
        const int* c = cs + (b << 9);
        int total = c[LL - 1];
        float4* dst = reinterpret_cast<float4*>(reg_out) + (size_t)gm * 64;
        if (m < total) {
            int lo = 0, hi = LL - 1;
            while (lo < hi) {
                int mid = (lo + hi) >> 1;
                if (c[mid] > m) hi = mid; else lo = mid + 1;
            }
            const float4* src = reinterpret_cast<const float4*>(x32) +
                                ((size_t)((b << 9) + lo)) * 64;
            dst[lane] = src[lane];
            dst[lane + 32] = src[lane + 32];
        } else {
            float4 z = make_float4(0.f, 0.f, 0.f, 0.f);
            dst[lane] = z;
            dst[lane + 32] = z;
        }
        return;
    }

    // ---------------- conv blocks ----------------
    const uint32_t sb = smem_u32(sm);
    const int wm = wid & 1;          // m half: rows wm*32..+31
    const int wn = wid >> 1;         // n eighth: cols wn*32..+31
    const int row0 = blockIdx.x * 64;
    const int l0 = row0 & 511;

    float* s_bias = (float*)(sm + S_PAR);
    float* s_g = (float*)(sm + S_PAR + 1024);
    float* s_be = (float*)(sm + S_PAR + 2048);
    float* s_lw = (float*)(sm + S_PAR + 3072);
    if (tid < 256) {
        s_bias[tid] = bias[tid];
        s_g[tid] = gamma[tid];
        s_be[tid] = beta[tid];
        s_lw[tid] = (mode == 1) ? lw[tid] : 0.f;
    }

    // resident A tile (66 rows x 512B) via cp.async
    for (int idx = tid; idx < 66 * 32; idx += 512) {
        int r = idx >> 5, c = idx & 31;
        int l = l0 - 1 + r;
        int v = ((unsigned)l < 512u) ? 1 : 0;
        long grow = (long)row0 - 1 + r;
        const __half* src = a_in + (v ? (grow * 256 + c * 8) : 0);
        cp16(sb + S_A + (uint32_t)(r * A_STR + c * 16), src, v);
    }
    cp_commit();

    // per-warp B fragment pointer: idx4 = (ks*16 + wn*2 + g)*32 + lane
    const uint4* Bw = Bf + (size_t)(wn * 2) * 32 + lane;

    // B prefetch ring (3 slots x 2 uint4, distance 2)
    uint4 bS[3][2];
#pragma unroll
    for (int g = 0; g < 2; g++) ldg128(bS[0][g], Bw + g * 32);
#pragma unroll
    for (int g = 0; g < 2; g++) ldg128(bS[1][g], Bw + 512 + g * 32);

    cp_wait0();
    __syncthreads();

    const uint32_t aL = sb + S_A +
        (uint32_t)((wm * 32 + (lane & 15)) * A_STR + (lane >> 4) * 16);

    float d[2][4][4];
#pragma unroll
    for (int tm = 0; tm < 2; tm++)
#pragma unroll
        for (int tn = 0; tn < 4; tn++)
#pragma unroll
            for (int j = 0; j < 4; j++) d[tm][tn][j] = 0.f;

    uint32_t aF[2][2][4];
#pragma unroll
    for (int tm = 0; tm < 2; tm++)
        ldsm4(aF[0][tm], aL + (uint32_t)(tm * 16 * A_STR));

    for (int kc = 0; kc < 8; kc++) {
#pragma unroll
        for (int s = 0; s < 6; s++) {
            const int ks = kc * 6 + s;
            // B prefetch ks+2
            if (ks + 2 < 48) {
                const uint4* bp = Bw + (size_t)(ks + 2) * 512;
#pragma unroll
                for (int g = 0; g < 2; g++)
                    ldg128(bS[(s + 2) % 3][g], bp + g * 32);
            }
            // A prefetch ks+1
            if (ks + 1 < 48) {
                const int kn = (ks + 1) / 6, sn = (ks + 1) % 6;
                const int tap = sn >> 1, ko = sn & 1;
#pragma unroll
                for (int tm = 0; tm < 2; tm++)
                    ldsm4(aF[(s + 1) & 1][tm],
                          aL + (uint32_t)(kn * 64 + (tm * 16 + tap) * A_STR +
                                          ko * 32));
            }
            // mma: slot s%3, A slot s&1
            const int sl = s % 3, ca = s & 1;
#pragma unroll
            for (int tm = 0; tm < 2; tm++)
#pragma unroll
                for (int g = 0; g < 2; g++) {
                    const uint32_t* bb = (const uint32_t*)&bS[sl][g];
                    mma16816(d[tm][2 * g], aF[ca][tm], bb);
                    mma16816(d[tm][2 * g + 1], aF[ca][tm], bb + 2);
                }
        }
    }

    __syncthreads();   // A region about to be reused as stats

    // -------- epilogue: accums -> smem stats, LN per row --------
    float* stats = (float*)(sm + S_A);       // 64 x 264 fp32
#pragma unroll
    for (int tm = 0; tm < 2; tm++) {
#pragma unroll
        for (int tn = 0; tn < 4; tn++) {
            int m = wm * 32 + tm * 16 + (lane >> 2);
            int n = wn * 32 + tn * 8 + (lane & 3) * 2;
            stats[m * 264 + n] = d[tm][tn][0] + s_bias[n];
            stats[m * 264 + n + 1] = d[tm][tn][1] + s_bias[n + 1];
            stats[(m + 8) * 264 + n] = d[tm][tn][2] + s_bias[n];
            stats[(m + 8) * 264 + n + 1] = d[tm][tn][3] + s_bias[n + 1];
        }
    }
    __syncthreads();

    // 8 threads per row: tid>>3 = row (0..63), tid&7 = 32-ch octant
    const int row = tid >> 3, q = tid & 7;
    const float* rp = stats + row * 264 + q * 32;
    float sum = 0.f, ssq = 0.f;
#pragma unroll
    for (int i = 0; i < 32; i++) {
        float v = rp[i];
        sum += v;
        ssq = fmaf(v, v, ssq);
    }
#pragma unroll
    for (int o = 1; o < 8; o <<= 1) {
        sum += __shfl_xor_sync(0xffffffffu, sum, o);
        ssq += __shfl_xor_sync(0xffffffffu, ssq, o);
    }
    float mu = sum * (1.f / 256.f);
    float rs = rsqrtf(ssq * (1.f / 256.f) - mu * mu + EPSV);

    if (mode == 1) {
        float dot = 0.f;
#pragma unroll
        for (int i = 0; i < 32; i++) {
            int c = q * 32 + i;
            float y = fmaxf((rp[i] - mu) * rs * s_g[c] + s_be[c], 0.f);
            dot = fmaf(y, s_lw[c], dot);
        }
#pragma unroll
        for (int o = 1; o < 8; o <<= 1)
            dot += __shfl_xor_sync(0xffffffffu, dot, o);
        if (q == 0) dup[row0 + row] = fmaxf(dot + lb[0], 0.f);
    } else {
#pragma unroll
        for (int v8 = 0; v8 < 4; v8++) {
            __half h[8];
#pragma unroll
            for (int j = 0; j < 8; j++) {
                int c = q * 32 + v8 * 8 + j;
                float y = fmaxf((rp[v8 * 8 + j] - mu) * rs * s_g[c] + s_be[c], 0.f);
                h[j] = __float2half(y);
            }
            size_t go = (size_t)(row0 + row) * 256 + q * 32 + v8 * 8;
            *(uint4*)(out_h + go) = *(uint4*)h;
        }
    }
}

// ---------------------------------------------------------------------------
extern "C" void kernel_launch(void* const* d_in, const int* in_sizes, int n_in,
                              void* d_out, int out_size) {
    const float* x      = (const float*)d_in[0];
    const int*   target = (const int*)d_in[1];
    const float* w1  = (const float*)d_in[3];
    const float* b1  = (const float*)d_in[4];
    const float* g1  = (const float*)d_in[5];
    const float* be1 = (const float*)d_in[6];
    const float* w2  = (const float*)d_in[7];
    const float* b2  = (const float*)d_in[8];
    const float* g2  = (const float*)d_in[9];
    const float* be2 = (const float*)d_in[10];
    const float* lw  = (const float*)d_in[11];
    const float* lb  = (const float*)d_in[12];

    float* out = (float*)d_out;
    float* dup = out + (size_t)BB * MM * DD;

    __half *xh, *h1h;
    uint4 *B1f, *B2f;
    int* cs;
    cudaGetSymbolAddress((void**)&xh, g_xh);
    cudaGetSymbolAddress((void**)&h1h, g_h1h);
    cudaGetSymbolAddress((void**)&B1f, g_B1f);
    cudaGetSymbolAddress((void**)&B2f, g_B2f);
    cudaGetSymbolAddress((void**)&cs, g_cs);

    cudaFuncSetAttribute((const void*)conv_mma,
                         cudaFuncAttributeMaxDynamicSharedMemorySize, S_TOTAL);

    prep_convert<<<(BB * LL * DD / 4 + 255) / 256, 256>>>(x, w1, w2);
    cumsum_k<<<BB, LL>>>(target, cs);

    // conv1 + fused regulate (blocks >= NCONV copy x -> out)
    conv_mma<<<NCONV + NREG, 512, S_TOTAL>>>(xh, B1f, b1, g1, be1, 0,
                                             h1h, lw, lb, dup, x, cs, out);
    // conv2 + fused linear
    conv_mma<<<NCONV, 512, S_TOTAL>>>(h1h, B2f, b2, g2, be2, 1,
                                      h1h, lw, lb, dup, x, cs, out);
}

// round 12
// speedup vs baseline: 1.1474x; 1.1474x over previous
#include <cuda_runtime.h>
#include <cuda_fp16.h>
#include <cstdint>

#define BB 16
#define LL 512
#define DD 256
#define FF 256
#define MM 2048
#define EPSV 1e-5f

// ---------------- device scratch ----------------
__device__ __align__(16) __half g_xh[BB * LL * DD];     // x in fp16
__device__ __align__(16) __half g_h1h[BB * LL * FF];    // conv1 output in fp16
// weights in mma-FRAGMENT order: uint4 index = (ks*16 + p)*32 + lane
__device__ __align__(16) uint4 g_B1f[48 * 16 * 32];
__device__ __align__(16) uint4 g_B2f[48 * 16 * 32];
__device__ int g_cs[BB * LL];

// ---------------- helpers ----------------
__device__ __forceinline__ uint32_t smem_u32(const void* p) {
    uint32_t a;
    asm("{ .reg .u64 t; cvta.to.shared.u64 t, %1; cvt.u32.u64 %0, t; }"
        : "=r"(a) : "l"(p));
    return a;
}

__device__ __forceinline__ void cp16(uint32_t dst, const void* src, int valid) {
    int sz = valid ? 16 : 0;
    asm volatile("cp.async.cg.shared.global [%0], [%1], %2, %3;"
                 :: "r"(dst), "l"(src), "n"(16), "r"(sz));
}
__device__ __forceinline__ void cp_commit() {
    asm volatile("cp.async.commit_group;" ::: "memory");
}
__device__ __forceinline__ void cp_wait0() {
    asm volatile("cp.async.wait_group 0;" ::: "memory");
}

__device__ __forceinline__ void ldsm4(uint32_t* r, uint32_t addr) {
    asm volatile("ldmatrix.sync.aligned.m8n8.x4.shared.b16 {%0,%1,%2,%3}, [%4];"
                 : "=r"(r[0]), "=r"(r[1]), "=r"(r[2]), "=r"(r[3]) : "r"(addr));
}

__device__ __forceinline__ void ldg128(uint4& v, const uint4* p) {
    asm volatile("ld.global.nc.v4.u32 {%0,%1,%2,%3}, [%4];"
                 : "=r"(v.x), "=r"(v.y), "=r"(v.z), "=r"(v.w) : "l"(p));
}

// fp16-accumulate HMMA: d,c are 2 x b32 (4 halves)
__device__ __forceinline__ void mma16816h(uint32_t* d, const uint32_t* a,
                                          const uint32_t* b) {
    asm volatile(
        "mma.sync.aligned.m16n8k16.row.col.f16.f16.f16.f16 "
        "{%0,%1}, {%2,%3,%4,%5}, {%6,%7}, {%0,%1};"
        : "+r"(d[0]), "+r"(d[1])
        : "r"(a[0]), "r"(a[1]), "r"(a[2]), "r"(a[3]), "r"(b[0]), "r"(b[1]));
}

// ---------------- prep: x -> fp16; weights -> fragment-order fp16 ----------
__global__ void prep_convert(const float* __restrict__ x,
                             const float* __restrict__ w1,
                             const float* __restrict__ w2) {
    int i4 = blockIdx.x * 256 + threadIdx.x;   // vec4 index
    if (i4 < BB * LL * DD / 4) {
        float4 v = reinterpret_cast<const float4*>(x)[i4];
        __half h[4];
        h[0] = __float2half(v.x);
        h[1] = __float2half(v.y);
        h[2] = __float2half(v.z);
        h[3] = __float2half(v.w);
        reinterpret_cast<uint2*>(g_xh)[i4] = *(uint2*)h;
    }
    if (i4 < 48 * 16 * 32) {
        int lane = i4 & 31;
        int rest = i4 >> 5;
        int p = rest & 15;
        int ks = rest >> 4;          // 0..47
        int kc = ks / 6, s = ks % 6;
        int tap = s >> 1, ko = s & 1;
        int l4 = lane & 3, lq = lane >> 2;
        int d0 = kc * 32 + ko * 16 + l4 * 2;
        int na = p * 16 + lq, nb = na + 8;
        auto pack = [&](const float* w, int n, int d) -> unsigned {
            __half2 h = __floats2half2_rn(w[n * 768 + d * 3 + tap],
                                          w[n * 768 + (d + 1) * 3 + tap]);
            return *(unsigned*)&h;
        };
        uint4 v1, v2;
        v1.x = pack(w1, na, d0);
        v1.y = pack(w1, na, d0 + 8);
        v1.z = pack(w1, nb, d0);
        v1.w = pack(w1, nb, d0 + 8);
        v2.x = pack(w2, na, d0);
        v2.y = pack(w2, na, d0 + 8);
        v2.z = pack(w2, nb, d0);
        v2.w = pack(w2, nb, d0 + 8);
        g_B1f[i4] = v1;
        g_B2f[i4] = v2;
    }
}

// ---------------- cumsum ----------------
__global__ void cumsum_k(const int* __restrict__ t, int* __restrict__ cs) {
    __shared__ int s[LL];
    int b = blockIdx.x, tid = threadIdx.x;
    s[tid] = t[(b << 9) + tid];
    __syncthreads();
    for (int off = 1; off < LL; off <<= 1) {
        int v = (tid >= off) ? s[tid - off] : 0;
        __syncthreads();
        s[tid] += v;
        __syncthreads();
    }
    cs[(b << 9) + tid] = s[tid];
}

// ---------------- length regulate (exact) ----------------
__global__ void regulate(const float* __restrict__ x,
                         const int* __restrict__ cs,
                         float* __restrict__ out) {
    int warp = threadIdx.x >> 5, lane = threadIdx.x & 31;
    int gm = blockIdx.x * 8 + warp;
    int b = gm >> 11;
    int m = gm & (MM - 1);
    const int* c = cs + (b << 9);
    int total = c[LL - 1];
    float4* dst = reinterpret_cast<float4*>(out) + (size_t)gm * 64;
    if (m < total) {
        int lo = 0, hi = LL - 1;
        while (lo < hi) {
            int mid = (lo + hi) >> 1;
            if (c[mid] > m) hi = mid; else lo = mid + 1;
        }
        const float4* src =
            reinterpret_cast<const float4*>(x) + ((size_t)((b << 9) + lo)) * 64;
        dst[lane] = src[lane];
        dst[lane + 32] = src[lane + 32];
    } else {
        float4 z = make_float4(0.f, 0.f, 0.f, 0.f);
        dst[lane] = z;
        dst[lane + 32] = z;
    }
}

// ---------------- fp16 conv(K=3): f16-accum HMMA + per-kc fp32 promote -----
// CTA: 64 rows x 256 channels; 8 warps (2m x 4n), warp tile 32x64.
// A smem-resident; B direct-LDG fragment stream; barrier-free k-loop.
#define S_PAR   0                  // bias/g/be/lw: 4 x 1KB
#define S_A     4096
#define A_STR   528
#define STATS_B (64 * 264 * 4)     // 67584 (overlaps A region)
#define S_TOTAL (4096 + STATS_B)   // 71680

__global__ void __launch_bounds__(256, 1)
conv_mma(const __half* __restrict__ a_in,
         const uint4* __restrict__ Bf,
         const float* __restrict__ bias,
         const float* __restrict__ gamma,
         const float* __restrict__ beta,
         int mode,
         __half* __restrict__ out_h,
         const float* __restrict__ lw,
         const float* __restrict__ lb,
         float* __restrict__ dup) {
    extern __shared__ char sm[];
    const uint32_t sb = smem_u32(sm);
    const int tid = threadIdx.x;
    const int lane = tid & 31;
    const int wid = tid >> 5;
    const int wm = wid & 1;
    const int wn = wid >> 1;
    const int row0 = blockIdx.x * 64;
    const int l0 = row0 & 511;

    float* s_bias = (float*)(sm + S_PAR);
    float* s_g = (float*)(sm + S_PAR + 1024);
    float* s_be = (float*)(sm + S_PAR + 2048);
    float* s_lw = (float*)(sm + S_PAR + 3072);
    s_bias[tid] = bias[tid];
    s_g[tid] = gamma[tid];
    s_be[tid] = beta[tid];
    s_lw[tid] = (mode == 1) ? lw[tid] : 0.f;

    // resident A tile (66 rows x 512B) via cp.async
    for (int idx = tid; idx < 66 * 32; idx += 256) {
        int r = idx >> 5, c = idx & 31;
        int l = l0 - 1 + r;
        int v = ((unsigned)l < 512u) ? 1 : 0;
        long grow = (long)row0 - 1 + r;
        const __half* src = a_in + (v ? (grow * 256 + c * 8) : 0);
        cp16(sb + S_A + (uint32_t)(r * A_STR + c * 16), src, v);
    }
    cp_commit();

    // per-warp B fragment pointer: idx4 = (ks*16 + wn*4 + g)*32 + lane
    const uint4* Bw = Bf + (size_t)(wn * 4) * 32 + lane;

    // B prefetch ring (3 slots, distance 2)
    uint4 bS[3][4];
#pragma unroll
    for (int g = 0; g < 4; g++) ldg128(bS[0][g], Bw + g * 32);
#pragma unroll
    for (int g = 0; g < 4; g++) ldg128(bS[1][g], Bw + 512 + g * 32);

    cp_wait0();
    __syncthreads();

    const uint32_t aL = sb + S_A +
        (uint32_t)((wm * 32 + (lane & 15)) * A_STR + (lane >> 4) * 16);

    float d[2][8][4];       // fp32 master accumulators
#pragma unroll
    for (int tm = 0; tm < 2; tm++)
#pragma unroll
        for (int tn = 0; tn < 8; tn++)
#pragma unroll
            for (int j = 0; j < 4; j++) d[tm][tn][j] = 0.f;

    uint32_t aF[2][2][4];
#pragma unroll
    for (int tm = 0; tm < 2; tm++)
        ldsm4(aF[0][tm], aL + (uint32_t)(tm * 16 * A_STR));

    for (int kc = 0; kc < 8; kc++) {
        uint32_t e[2][8][2];    // fp16 accumulators for this kc chunk
#pragma unroll
        for (int tm = 0; tm < 2; tm++)
#pragma unroll
            for (int tn = 0; tn < 8; tn++) {
                e[tm][tn][0] = 0u;
                e[tm][tn][1] = 0u;
            }
#pragma unroll
        for (int s = 0; s < 6; s++) {
            const int ks = kc * 6 + s;
            // B prefetch ks+2
            if (ks + 2 < 48) {
                const uint4* bp = Bw + (size_t)(ks + 2) * 512;
#pragma unroll
                for (int g = 0; g < 4; g++)
                    ldg128(bS[(s + 2) % 3][g], bp + g * 32);
            }
            // A prefetch ks+1
            if (ks + 1 < 48) {
                const int kn = (ks + 1) / 6, sn = (ks + 1) % 6;
                const int tap = sn >> 1, ko = sn & 1;
#pragma unroll
                for (int tm = 0; tm < 2; tm++)
                    ldsm4(aF[(s + 1) & 1][tm],
                          aL + (uint32_t)(kn * 64 + (tm * 16 + tap) * A_STR +
                                          ko * 32));
            }
            // f16-accum mma: slot s%3, A slot s&1
            const int sl = s % 3, ca = s & 1;
#pragma unroll
            for (int tm = 0; tm < 2; tm++)
#pragma unroll
                for (int g = 0; g < 4; g++) {
                    const uint32_t* bb = (const uint32_t*)&bS[sl][g];
                    mma16816h(e[tm][2 * g], aF[ca][tm], bb);
                    mma16816h(e[tm][2 * g + 1], aF[ca][tm], bb + 2);
                }
        }
        // promote fp16 chunk accumulators into fp32
#pragma unroll
        for (int tm = 0; tm < 2; tm++)
#pragma unroll
            for (int tn = 0; tn < 8; tn++) {
                float2 f0 = __half22float2(*(const __half2*)&e[tm][tn][0]);
                float2 f1 = __half22float2(*(const __half2*)&e[tm][tn][1]);
                d[tm][tn][0] += f0.x;
                d[tm][tn][1] += f0.y;
                d[tm][tn][2] += f1.x;
                d[tm][tn][3] += f1.y;
            }
    }

    __syncthreads();   // A region about to be reused as stats

    // -------- epilogue: accums -> smem stats, LN per row --------
    float* stats = (float*)(sm + S_A);       // 64 x 264 fp32
#pragma unroll
    for (int tm = 0; tm < 2; tm++) {
#pragma unroll
        for (int tn = 0; tn < 8; tn++) {
            int m = wm * 32 + tm * 16 + (lane >> 2);
            int n = wn * 64 + tn * 8 + (lane & 3) * 2;
            stats[m * 264 + n] = d[tm][tn][0] + s_bias[n];
            stats[m * 264 + n + 1] = d[tm][tn][1] + s_bias[n + 1];
            stats[(m + 8) * 264 + n] = d[tm][tn][2] + s_bias[n];
            stats[(m + 8) * 264 + n + 1] = d[tm][tn][3] + s_bias[n + 1];
        }
    }
    __syncthreads();

    const int row = tid >> 2, q = tid & 3;
    const float* rp = stats + row * 264 + q * 64;
    float sum = 0.f, ssq = 0.f;
#pragma unroll 8
    for (int i = 0; i < 64; i++) {
        float v = rp[i];
        sum += v;
        ssq = fmaf(v, v, ssq);
    }
    sum += __shfl_xor_sync(0xffffffffu, sum, 1);
    ssq += __shfl_xor_sync(0xffffffffu, ssq, 1);
    sum += __shfl_xor_sync(0xffffffffu, sum, 2);
    ssq += __shfl_xor_sync(0xffffffffu, ssq, 2);
    float mu = sum * (1.f / 256.f);
    float rs = rsqrtf(ssq * (1.f / 256.f) - mu * mu + EPSV);

    if (mode == 1) {
        float dot = 0.f;
#pragma unroll 8
        for (int i = 0; i < 64; i++) {
            int c = q * 64 + i;
            float y = fmaxf((rp[i] - mu) * rs * s_g[c] + s_be[c], 0.f);
            dot = fmaf(y, s_lw[c], dot);
        }
        dot += __shfl_xor_sync(0xffffffffu, dot, 1);
        dot += __shfl_xor_sync(0xffffffffu, dot, 2);
        if (q == 0) dup[row0 + row] = fmaxf(dot + lb[0], 0.f);
    } else {
#pragma unroll
        for (int v8 = 0; v8 < 8; v8++) {
            __half h[8];
#pragma unroll
            for (int j = 0; j < 8; j++) {
                int c = q * 64 + v8 * 8 + j;
                float y = fmaxf((rp[v8 * 8 + j] - mu) * rs * s_g[c] + s_be[c], 0.f);
                h[j] = __float2half(y);
            }
            size_t go = (size_t)(row0 + row) * 256 + q * 64 + v8 * 8;
            *(uint4*)(out_h + go) = *(uint4*)h;
        }
    }
}

// ---------------------------------------------------------------------------
extern "C" void kernel_launch(void* const* d_in, const int* in_sizes, int n_in,
                              void* d_out, int out_size) {
    const float* x      = (const float*)d_in[0];
    const int*   target = (const int*)d_in[1];
    const float* w1  = (const float*)d_in[3];
    const float* b1  = (const float*)d_in[4];
    const float* g1  = (const float*)d_in[5];
    const float* be1 = (const float*)d_in[6];
    const float* w2  = (const float*)d_in[7];
    const float* b2  = (const float*)d_in[8];
    const float* g2  = (const float*)d_in[9];
    const float* be2 = (const float*)d_in[10];
    const float* lw  = (const float*)d_in[11];
    const float* lb  = (const float*)d_in[12];

    float* out = (float*)d_out;
    float* dup = out + (size_t)BB * MM * DD;

    __half *xh, *h1h;
    uint4 *B1f, *B2f;
    int* cs;
    cudaGetSymbolAddress((void**)&xh, g_xh);
    cudaGetSymbolAddress((void**)&h1h, g_h1h);
    cudaGetSymbolAddress((void**)&B1f, g_B1f);
    cudaGetSymbolAddress((void**)&B2f, g_B2f);
    cudaGetSymbolAddress((void**)&cs, g_cs);

    cudaFuncSetAttribute((const void*)conv_mma,
                         cudaFuncAttributeMaxDynamicSharedMemorySize, S_TOTAL);

    prep_convert<<<(BB * LL * DD / 4 + 255) / 256, 256>>>(x, w1, w2);
    cumsum_k<<<BB, LL>>>(target, cs);
    regulate<<<BB * MM / 8, 256>>>(x, cs, out);

    conv_mma<<<BB * LL / 64, 256, S_TOTAL>>>(xh, B1f, b1, g1, be1, 0,
                                             h1h, lw, lb, dup);
    conv_mma<<<BB * LL / 64, 256, S_TOTAL>>>(h1h, B2f, b2, g2, be2, 1,
                                             h1h, lw, lb, dup);
}